// round 6
// baseline (speedup 1.0000x reference)
#include <cuda_runtime.h>
#include <cstdint>
#include <math.h>

// NaiveFourierKANLayer via int8 mma.sync (m16n8k32, s32 accum), 2-level quantization.
// y[b,j] = sum_{i,g} cos(x_bi*(g+1))W0 + sin(x_bi*(g+1))W1 + bias
// A (cos/sin) generated by rotation recurrence + quantized in-kernel.
// B pre-quantized to 2-level s8 by conv kernel. 3 integer terms:
// y = (128*S(ah*bh) + S(ah*bl) + S(al*bh)) * SQ/(127*128)

#define NI 256
#define NG 300
#define NO 256
#define SPLITK 4
#define IPC (NI/SPLITK)       // 64 i per CTA
#define NGC 10                // 32-g chunks per i (chunk 9 padded)
#define NSTAGE (IPC*NGC)      // 640

#define RSB 80                // smem row pitch (64 data bytes + pad) conflict-free
#define A_HI 0
#define A_LO 10240
#define B_HI 20480
#define B_LO 25600
#define STAGE_BYTES 30720
#define DYN_SMEM (2*STAGE_BYTES)   // 61440

// SQ = 8*sigma/127, sigma = 1/(sqrt(256)*sqrt(300))
#define SQF 2.2730326e-4f
#define INV_SQ 4399.4023f            // 1/SQF
#define FSCALE 1.3982976e-8f         // SQF/(127*128)

__device__ float    g_scratch[SPLITK * 1024 * 256];          // 4 MB
__device__ uint32_t g_B2h[256u*256u*10u*16u];                // 41.9 MB (s8 hi, packed u32)
__device__ uint32_t g_B2l[256u*256u*10u*16u];                // 41.9 MB (s8 lo)

// ---------------- helpers ----------------
__device__ __forceinline__ uint32_t smem_u32(const void* p) {
    uint32_t a;
    asm("{ .reg .u64 t; cvta.to.shared.u64 t, %1; cvt.u32.u64 %0, t; }" : "=r"(a) : "l"(p));
    return a;
}
__device__ __forceinline__ uint32_t pack4(int b0, int b1, int b2, int b3) {
    uint32_t t, r;
    asm("cvt.pack.sat.s8.s32.b32 %0, %1, %2, 0;"  : "=r"(t) : "r"(b3), "r"(b2));
    asm("cvt.pack.sat.s8.s32.b32 %0, %1, %2, %3;" : "=r"(r) : "r"(b1), "r"(b0), "r"(t));
    return r;   // byte0=b0 .. byte3=b3
}
// 2-level quantize: v in [-1,1] -> h + l/128 (scale 127)
__device__ __forceinline__ void q2a(float v, int& h, int& l) {
    const float f = v * 127.0f;
    h = __float2int_rn(f);
    l = __float2int_rn((f - (float)h) * 128.0f);
}
__device__ __forceinline__ void rotstep(float& c, float& s, float cr, float sr) {
    float nc = fmaf(c, cr, -(s * sr));
    float ns = fmaf(s, cr, c * sr);
    c = nc; s = ns;
}

#define LDSM4(r0,r1,r2,r3,addr)                                                  \
    asm volatile("ldmatrix.sync.aligned.m8n8.x4.shared.b16 {%0,%1,%2,%3}, [%4];" \
        : "=r"(r0), "=r"(r1), "=r"(r2), "=r"(r3) : "r"(addr))

#define IMMA(d,a,b0,b1)                                                       \
    asm volatile("mma.sync.aligned.m16n8k32.row.col.s32.s8.s8.s32 "           \
        "{%0,%1,%2,%3},{%4,%5,%6,%7},{%8,%9},{%0,%1,%2,%3};"                  \
        : "+r"((d)[0]), "+r"((d)[1]), "+r"((d)[2]), "+r"((d)[3])              \
        : "r"((a)[0]), "r"((a)[1]), "r"((a)[2]), "r"((a)[3]), "r"(b0), "r"(b1))

#define CP16(dst,src) \
    asm volatile("cp.async.cg.shared.global [%0], [%1], 16;" :: "r"(dst), "l"(src))
#define CP_COMMIT() asm volatile("cp.async.commit_group;" ::: "memory")
#define CP_WAIT0()  asm volatile("cp.async.wait_group 0;" ::: "memory")

extern __shared__ char dsmem[];

// ---------------- B pre-quantization: fp32 -> 2-level s8 ----------------
__global__ void __launch_bounds__(512, 2)
fkan_conv(const float* __restrict__ fc)
{
    const int idx  = blockIdx.x * 512 + threadIdx.x;   // 10,485,760
    const int quad = idx & 7;
    const int sect = (idx >> 3) & 1;                   // 0=cos/W0, 1=sin/W1
    const int rest = idx >> 4;
    const int gc   = rest % NGC;
    const int i    = (rest / NGC) & 255;
    const int j    = rest / (NGC * 256);

    const int g0 = gc * 32 + quad * 4;
    const float* src = fc + ((size_t)(sect * NO + j) * NI + i) * NG;

    int h[4], l[4];
    #pragma unroll
    for (int e = 0; e < 4; ++e) {
        float w = (g0 + e < NG) ? src[g0 + e] : 0.f;
        float f = w * INV_SQ;
        f = fminf(fmaxf(f, -127.f), 127.f);
        h[e] = __float2int_rn(f);
        l[e] = __float2int_rn((f - (float)h[e]) * 128.0f);
    }
    const uint32_t di = (((uint32_t)j * 256u + (uint32_t)i) * 10u + (uint32_t)gc) * 16u
                      + (uint32_t)sect * 8u + (uint32_t)quad;
    g_B2h[di] = pack4(h[0], h[1], h[2], h[3]);
    g_B2l[di] = pack4(l[0], l[1], l[2], l[3]);
}

// ---------------- main IMMA kernel ----------------
__global__ void __launch_bounds__(256, 1)
fkan_imma(const float* __restrict__ x)
{
    const int tid  = threadIdx.x;
    const int lane = tid & 31;
    const int w    = tid >> 5;
    const int ks = blockIdx.x;             // split-K slice (i block)
    const int m0 = blockIdx.y * 128;       // batch-row tile
    const int n0 = blockIdx.z * 64;        // output-col tile

    const uint32_t smb = smem_u32(dsmem);

    // producer maps
    const int rr = tid >> 1, q = tid & 1;          // A: row, g-half(16)
    const int lev = tid >> 7, jj = (tid >> 1) & 63, half = tid & 1;   // B cp map
    const uint32_t* bsrc = (lev ? g_B2l : g_B2h)
                         + ((uint32_t)(n0 + jj) * 256u) * 160u;       // + i*160 later
    const uint32_t bdst0 = (uint32_t)(lev ? B_LO : B_HI)
                         + (uint32_t)jj * RSB + (uint32_t)half * 32u;

    // mma maps: 8 warps = 2(M) x 4(N); warp tile 64x16
    const int wm = w & 1, wn = w >> 1;
    const uint32_t aoff = (uint32_t)(wm*64 + (lane & 7) + ((lane >> 3) & 1)*8) * RSB
                        + (uint32_t)(lane >> 4) * 16;
    const uint32_t boff = (uint32_t)(wn*16 + (lane & 7) + ((lane >> 3) & 1)*8) * RSB
                        + (uint32_t)(lane >> 4) * 16;

    int   acc1[4][2][4], acc2[4][2][4];
    float accF[4][2][4];
    #pragma unroll
    for (int a = 0; a < 4; ++a)
        #pragma unroll
        for (int b = 0; b < 2; ++b)
            #pragma unroll
            for (int c = 0; c < 4; ++c) { acc1[a][b][c] = 0; acc2[a][b][c] = 0; accF[a][b][c] = 0.f; }

    const float* xcol = x + (size_t)(m0 + rr) * NI + ks * IPC;

    // prologue: B copies for stage 0
    {
        const uint32_t* src = bsrc + (uint32_t)(ks * IPC) * 160u + (uint32_t)half * 8u;
        const uint32_t d0 = smb + bdst0;
        CP16(d0,      src);
        CP16(d0 + 16, src + 4);
        CP_COMMIT();
    }

    int it = 0;
    for (int ii = 0; ii < IPC; ++ii) {
        const float t = xcol[ii];
        float s1, c1;
        sincosf(t, &s1, &c1);
        const float c2 = fmaf(c1, c1, -(s1*s1)), s2 = 2.f*c1*s1;
        const float c4 = fmaf(c2, c2, -(s2*s2)), s4 = 2.f*c2*s2;
        const float c8 = fmaf(c4, c4, -(s4*s4)), s8 = 2.f*c4*s4;
        const float c16 = fmaf(c8, c8, -(s8*s8)), s16 = 2.f*c8*s8;
        // state at angle (q*16 + 1)*t
        float cc, ss;
        if (q) { cc = fmaf(c1, c16, -(s1*s16)); ss = fmaf(s1, c16, c1*s16); }
        else   { cc = c1; ss = s1; }

        for (int gc = 0; gc < NGC; ++gc, ++it) {
            const uint32_t stg = (uint32_t)(it & 1) * STAGE_BYTES;
            char* sm = dsmem + stg;

            // ---- generate + quantize + STS A: 16 g per thread, 4-adjacent groups ----
            #pragma unroll
            for (int m = 0; m < 4; ++m) {
                int ch[4], cl[4], sh[4], sl[4];
                #pragma unroll
                for (int e = 0; e < 4; ++e) {
                    const int gg = gc*32 + q*16 + 4*m + e;
                    const float a = (gg < NG) ? cc : 0.f;
                    const float b = (gg < NG) ? ss : 0.f;
                    q2a(a, ch[e], cl[e]);
                    q2a(b, sh[e], sl[e]);
                    rotstep(cc, ss, c1, s1);
                }
                const uint32_t off = (uint32_t)rr * RSB + (uint32_t)(q*16 + 4*m);
                *(uint32_t*)(sm + A_HI + off)      = pack4(ch[0], ch[1], ch[2], ch[3]);
                *(uint32_t*)(sm + A_LO + off)      = pack4(cl[0], cl[1], cl[2], cl[3]);
                *(uint32_t*)(sm + A_HI + off + 32) = pack4(sh[0], sh[1], sh[2], sh[3]);
                *(uint32_t*)(sm + A_LO + off + 32) = pack4(sl[0], sl[1], sl[2], sl[3]);
            }
            // jump +16t over the other half to next chunk start
            { const float nc = fmaf(cc, c16, -(ss*s16));
              ss = fmaf(ss, c16, cc*s16); cc = nc; }

            CP_WAIT0();              // B(it) landed
            __syncthreads();         // A visible + all MMA(it-1) done

            // ---- issue B copies for stage it+1 ----
            if (it + 1 < NSTAGE) {
                const int nit = it + 1;
                const int nii = nit / NGC, ngc2 = nit % NGC;
                const uint32_t* src = bsrc + (uint32_t)(ks * IPC + nii) * 160u
                                    + (uint32_t)ngc2 * 16u + (uint32_t)half * 8u;
                const uint32_t d0 = smb + (uint32_t)((nit & 1) * STAGE_BYTES) + bdst0;
                CP16(d0,      src);
                CP16(d0 + 16, src + 4);
                CP_COMMIT();
            }

            // ---- consume: 2 k32-steps, term-grouped ----
            const uint32_t pA = smb + stg + aoff;
            const uint32_t pB = smb + stg + B_HI + boff;
            #pragma unroll
            for (int kk = 0; kk < 2; ++kk) {
                uint32_t bh4[4], bl4[4];
                LDSM4(bh4[0], bh4[1], bh4[2], bh4[3], pB + kk*32);
                LDSM4(bl4[0], bl4[1], bl4[2], bl4[3], pB + (B_LO - B_HI) + kk*32);
                uint32_t ah[4][4], al[4][4];
                #pragma unroll
                for (int mf = 0; mf < 4; ++mf) {
                    LDSM4(ah[mf][0], ah[mf][1], ah[mf][2], ah[mf][3],
                          pA + mf*(16*RSB) + kk*32);
                    LDSM4(al[mf][0], al[mf][1], al[mf][2], al[mf][3],
                          pA + A_LO + mf*(16*RSB) + kk*32);
                }
                // b regs: nf0 = {t0,t2}, nf1 = {t1,t3}
                #pragma unroll
                for (int mf = 0; mf < 4; ++mf) {
                    IMMA(acc1[mf][0], ah[mf], bh4[0], bh4[2]);
                    IMMA(acc1[mf][1], ah[mf], bh4[1], bh4[3]);
                }
                #pragma unroll
                for (int mf = 0; mf < 4; ++mf) {
                    IMMA(acc2[mf][0], ah[mf], bl4[0], bl4[2]);
                    IMMA(acc2[mf][1], ah[mf], bl4[1], bl4[3]);
                }
                #pragma unroll
                for (int mf = 0; mf < 4; ++mf) {
                    IMMA(acc2[mf][0], al[mf], bh4[0], bh4[2]);
                    IMMA(acc2[mf][1], al[mf], bh4[1], bh4[3]);
                }
            }

            // ---- merge s32 -> fp32 master every 16 stages (overflow-safe) ----
            if ((it & 15) == 15) {
                #pragma unroll
                for (int mf = 0; mf < 4; ++mf)
                    #pragma unroll
                    for (int nf = 0; nf < 2; ++nf)
                        #pragma unroll
                        for (int c = 0; c < 4; ++c) {
                            accF[mf][nf][c] = fmaf(128.f, (float)acc1[mf][nf][c],
                                                   accF[mf][nf][c]) + (float)acc2[mf][nf][c];
                            acc1[mf][nf][c] = 0; acc2[mf][nf][c] = 0;
                        }
            }
        }
    }
    // final merge (no-op if already merged; accs are zero then)
    #pragma unroll
    for (int mf = 0; mf < 4; ++mf)
        #pragma unroll
        for (int nf = 0; nf < 2; ++nf)
            #pragma unroll
            for (int c = 0; c < 4; ++c)
                accF[mf][nf][c] = fmaf(128.f, (float)acc1[mf][nf][c],
                                       accF[mf][nf][c]) + (float)acc2[mf][nf][c];

    // ---- epilogue -> split-K scratch ----
    float* dst = g_scratch + ((size_t)ks << 18);
    #pragma unroll
    for (int mf = 0; mf < 4; ++mf) {
        const int r = m0 + wm*64 + mf*16 + (lane >> 2);
        #pragma unroll
        for (int nf = 0; nf < 2; ++nf) {
            const int c = n0 + wn*16 + nf*8 + (lane & 3)*2;
            float2 v0, v1;
            v0.x = accF[mf][nf][0] * FSCALE; v0.y = accF[mf][nf][1] * FSCALE;
            v1.x = accF[mf][nf][2] * FSCALE; v1.y = accF[mf][nf][3] * FSCALE;
            *(float2*)(dst + (size_t)r * NO + c)       = v0;
            *(float2*)(dst + (size_t)(r + 8) * NO + c) = v1;
        }
    }
}

__global__ void __launch_bounds__(512, 1)
fkan_reduce(const float* __restrict__ bias, float* __restrict__ out)
{
    const int idx = blockIdx.x * 512 + threadIdx.x;
    float a = bias[idx & 255];
    #pragma unroll
    for (int k = 0; k < SPLITK; ++k)
        a += g_scratch[((size_t)k << 18) + idx];
    out[idx] = a;
}

extern "C" void kernel_launch(void* const* d_in, const int* in_sizes, int n_in,
                              void* d_out, int out_size) {
    const float* x    = (const float*)d_in[0];
    const float* fc   = (const float*)d_in[1];
    const float* bias = (const float*)d_in[2];
    float* out        = (float*)d_out;

    cudaFuncSetAttribute(fkan_imma, cudaFuncAttributeMaxDynamicSharedMemorySize, DYN_SMEM);
    fkan_conv<<<20480, 512>>>(fc);
    fkan_imma<<<dim3(SPLITK, 8, 4), 256, DYN_SMEM>>>(x);
    fkan_reduce<<<512, 512>>>(bias, out);
}

// round 7
// speedup vs baseline: 3.1772x; 3.1772x over previous
#include <cuda_runtime.h>
#include <cstdint>
#include <math.h>

// NaiveFourierKANLayer via warp-level fp16 mma.sync, 2-term split:
//   y = sum_k Ah(k) * (Bh(k) + Bl(k)),  A=cos/sin generated fp16,
//   B = coeffs * 2048 split hi/lo fp16 (scale dodges fp16 subnormals in Bl).
// MMA terms: 2 (vs 3 in bf16 R4 kernel) -> ~2/3 tensor time.
// Skip all-zero kk sub-steps in the padded last g-chunk (-5% MMAs).

#define NI 256
#define NG 300
#define NO 256
#define SPLITK 8
#define IPC (NI/SPLITK)      // 32 i per CTA
#define NGC 10               // 32-g chunks per i (chunk 9 zero-padded)

#define RSB 144              // smem row pitch bytes -> conflict-free ldmatrix
#define A_HI 0
#define B_HI 18432
#define B_LO 36864
#define STAGE_BYTES 55296
#define DYN_SMEM (2*STAGE_BYTES)   // 110592

#define BSCALE 2048.0f
#define FSCALE (1.0f/2048.0f)

__device__ float g_scratch[SPLITK * 1024 * 256];   // 8 MB split-K partials

// ---------------- helpers ----------------
__device__ __forceinline__ uint32_t smem_u32(const void* p) {
    uint32_t a;
    asm("{ .reg .u64 t; cvta.to.shared.u64 t, %1; cvt.u32.u64 %0, t; }" : "=r"(a) : "l"(p));
    return a;
}
// packf16(a,b): low f16 = a (even k), high f16 = b (odd k)
__device__ __forceinline__ uint32_t packf16(float a, float b) {
    uint32_t r;
    asm("cvt.rn.f16x2.f32 %0, %2, %1;" : "=r"(r) : "f"(a), "f"(b));
    return r;
}
__device__ __forceinline__ void unpackf16(uint32_t p, float& lo, float& hi) {
    asm("{ .reg .b16 l,h; mov.b32 {l,h}, %2; cvt.f32.f16 %0, l; cvt.f32.f16 %1, h; }"
        : "=f"(lo), "=f"(hi) : "r"(p));
}

#define LDSM4(r0,r1,r2,r3,addr)                                                  \
    asm volatile("ldmatrix.sync.aligned.m8n8.x4.shared.b16 {%0,%1,%2,%3}, [%4];" \
        : "=r"(r0), "=r"(r1), "=r"(r2), "=r"(r3) : "r"(addr))

#define MMA(d,a,b0,b1)                                                        \
    asm volatile("mma.sync.aligned.m16n8k16.row.col.f32.f16.f16.f32 "         \
        "{%0,%1,%2,%3},{%4,%5,%6,%7},{%8,%9},{%0,%1,%2,%3};"                  \
        : "+f"((d)[0]), "+f"((d)[1]), "+f"((d)[2]), "+f"((d)[3])              \
        : "r"((a)[0]), "r"((a)[1]), "r"((a)[2]), "r"((a)[3]), "r"(b0), "r"(b1))

extern __shared__ char dsmem[];

__global__ void __launch_bounds__(256, 1)
fkan_hmma(const float* __restrict__ x, const float* __restrict__ fc)
{
    const int tid  = threadIdx.x;
    const int lane = tid & 31;
    const int w    = tid >> 5;
    const int ks = blockIdx.x;            // split-K slice (i block)
    const int m0 = blockIdx.y * 128;      // batch-row tile
    const int n0 = blockIdx.z * 128;      // output-col tile

    const uint32_t smb = smem_u32(dsmem);

    // producer maps
    const int rr = tid >> 1, q = tid & 1;        // A-gen: row, g-half
    const int bt = tid >> 7, bj = tid & 127;     // B: trig part, j-row

    // mma maps: 8 warps = 2(M) x 4(N); warp tile 64x32
    const int wm = w & 1, wn = w >> 1;
    const uint32_t aoff = (uint32_t)(wm*64 + (lane & 7) + ((lane >> 3) & 1)*8) * RSB
                        + (uint32_t)(lane >> 4) * 16;
    const uint32_t boff = (uint32_t)(wn*32 + (lane & 7) + (lane >> 4)*8) * RSB
                        + (uint32_t)((lane >> 3) & 1) * 16;

    float acc[4][4][4];
    #pragma unroll
    for (int a = 0; a < 4; ++a)
        #pragma unroll
        for (int b = 0; b < 4; ++b)
            #pragma unroll
            for (int c = 0; c < 4; ++c) acc[a][b][c] = 0.f;

    const float* xcol  = x + (size_t)(m0 + rr) * NI + ks * IPC;
    const float* bbase = fc + ((size_t)(bt * NO + n0 + bj) * NI + ks * IPC) * NG;

    // B stage prefetch registers (32 fp32)
    float4 bf[8];
    {
        const float* p = bbase;            // ii=0, gc=0
        #pragma unroll
        for (int q4 = 0; q4 < 8; ++q4) bf[q4] = *(const float4*)(p + q4*4);
    }

    int it = 0;
    for (int ii = 0; ii < IPC; ++ii) {
        // rotation setup for this i
        const float t = xcol[ii];
        float s1, c1;
        sincosf(t, &s1, &c1);
        const float c2 = fmaf(c1, c1, -(s1*s1)), s2 = 2.f*c1*s1;
        const float c4 = fmaf(c2, c2, -(s2*s2)), s4 = 2.f*c2*s2;
        const float c8 = fmaf(c4, c4, -(s4*s4)), s8 = 2.f*c4*s4;
        const float c16 = fmaf(c8, c8, -(s8*s8)), s16 = 2.f*c8*s8;
        // state at angle (q*16 + 1)*t
        float cc, ss;
        if (q) { cc = fmaf(c1, c16, -(s1*s16)); ss = fmaf(s1, c16, c1*s16); }
        else   { cc = c1; ss = s1; }

        for (int gc = 0; gc < NGC; ++gc, ++it) {
            char* sm = dsmem + (it & 1) * STAGE_BYTES;

            // ---- STS B (from prefetched regs, x2048, hi/lo): k = bt*32 + g ----
            {
                const float* bv = (const float*)bf;
                #pragma unroll
                for (int pp = 0; pp < 16; ++pp) {
                    const float a = bv[2*pp] * BSCALE, b = bv[2*pp+1] * BSCALE;
                    const uint32_t hp = packf16(a, b);
                    float alo, bhi;
                    unpackf16(hp, alo, bhi);
                    const uint32_t lp = packf16(a - alo, b - bhi);
                    const uint32_t off = (uint32_t)bj * RSB + (uint32_t)(bt*32 + 2*pp) * 2;
                    *(uint32_t*)(sm + B_HI + off) = hp;
                    *(uint32_t*)(sm + B_LO + off) = lp;
                }
            }
            // ---- generate + STS A (single fp16): cos at k=gl, sin at k=32+gl ----
            #pragma unroll
            for (int m = 0; m < 8; ++m) {
                const int gl = q*16 + 2*m;
                const int gg = gc*32 + gl;          // harmonic gg+1
                float ce = cc, se = ss;
                float co = fmaf(cc, c1, -(ss*s1));
                float so = fmaf(ss, c1,  cc*s1);
                if (gg     >= NG) { ce = 0.f; se = 0.f; }
                if (gg + 1 >= NG) { co = 0.f; so = 0.f; }
                const uint32_t offc = (uint32_t)rr * RSB + (uint32_t)gl * 2;
                *(uint32_t*)(sm + A_HI + offc)      = packf16(ce, co);
                *(uint32_t*)(sm + A_HI + offc + 64) = packf16(se, so);
                // advance pair start by 2t
                const float nc = fmaf(cc, c2, -(ss*s2));
                ss = fmaf(ss, c2, cc*s2); cc = nc;
            }
            // jump +16t over the other half to next 32-g chunk
            { const float nc = fmaf(cc, c16, -(ss*s16));
              ss = fmaf(ss, c16, cc*s16); cc = nc; }

            __syncthreads();

            // ---- prefetch next stage's B (hidden under HMMA) ----
            if (it + 1 < IPC * NGC) {
                const int nit = it + 1;
                const int nii = nit / NGC, ngc = nit % NGC;
                const float* p = bbase + (size_t)nii * NG + ngc * 32;
                #pragma unroll
                for (int q4 = 0; q4 < 8; ++q4) {
                    const int gg = ngc*32 + q4*4;
                    bf[q4] = (gg < NG) ? *(const float4*)(p + q4*4)
                                       : make_float4(0.f, 0.f, 0.f, 0.f);
                }
            }

            // ---- consume: 4 K-steps x (4 mf x 4 n8) x 2 terms ----
            // gc==9: k 12..31 (kk=1) and k 44..63 (kk=3) are all zero -> skip
            const uint32_t pA = smb + (uint32_t)(it & 1) * STAGE_BYTES + aoff;
            const uint32_t pB = smb + (uint32_t)(it & 1) * STAGE_BYTES + B_HI + boff;
            const int kkstep = (gc == 9) ? 2 : 1;
            #pragma unroll 4
            for (int kk = 0; kk < 4; kk += kkstep) {
                uint32_t bh[8], bl[8];
                LDSM4(bh[0], bh[1], bh[2], bh[3], pB + kk*32);
                LDSM4(bh[4], bh[5], bh[6], bh[7], pB + 16*RSB + kk*32);
                LDSM4(bl[0], bl[1], bl[2], bl[3], pB + (B_LO - B_HI) + kk*32);
                LDSM4(bl[4], bl[5], bl[6], bl[7], pB + (B_LO - B_HI) + 16*RSB + kk*32);
                uint32_t ah[4][4];
                #pragma unroll
                for (int mf = 0; mf < 4; ++mf)
                    LDSM4(ah[mf][0], ah[mf][1], ah[mf][2], ah[mf][3],
                          pA + mf*(16*RSB) + kk*32);
                #pragma unroll
                for (int mf = 0; mf < 4; ++mf)
                    #pragma unroll
                    for (int f = 0; f < 4; ++f) {
                        const int bi = (f >> 1)*4 + (f & 1)*2;
                        MMA(acc[mf][f], ah[mf], bh[bi], bh[bi+1]);   // Ah*Bhi
                    }
                #pragma unroll
                for (int mf = 0; mf < 4; ++mf)
                    #pragma unroll
                    for (int f = 0; f < 4; ++f) {
                        const int bi = (f >> 1)*4 + (f & 1)*2;
                        MMA(acc[mf][f], ah[mf], bl[bi], bl[bi+1]);   // Ah*Blo
                    }
            }
        }
    }

    // ---- epilogue: accumulators (x2048) -> split-K scratch ----
    float* dst = g_scratch + ((size_t)ks << 18);
    #pragma unroll
    for (int mf = 0; mf < 4; ++mf) {
        const int r = m0 + wm*64 + mf*16 + (lane >> 2);
        #pragma unroll
        for (int f = 0; f < 4; ++f) {
            const int c = n0 + wn*32 + f*8 + (lane & 3)*2;
            float2 v0, v1;
            v0.x = acc[mf][f][0] * FSCALE; v0.y = acc[mf][f][1] * FSCALE;
            v1.x = acc[mf][f][2] * FSCALE; v1.y = acc[mf][f][3] * FSCALE;
            *(float2*)(dst + (size_t)r * NO + c)       = v0;
            *(float2*)(dst + (size_t)(r + 8) * NO + c) = v1;
        }
    }
}

__global__ void __launch_bounds__(512, 1)
fkan_reduce(const float* __restrict__ bias, float* __restrict__ out)
{
    const int idx = blockIdx.x * 512 + threadIdx.x;
    float a = bias[idx & 255];
    #pragma unroll
    for (int k = 0; k < SPLITK; ++k)
        a += g_scratch[((size_t)k << 18) + idx];
    out[idx] = a;
}

extern "C" void kernel_launch(void* const* d_in, const int* in_sizes, int n_in,
                              void* d_out, int out_size) {
    const float* x    = (const float*)d_in[0];
    const float* fc   = (const float*)d_in[1];
    const float* bias = (const float*)d_in[2];
    float* out        = (float*)d_out;

    cudaFuncSetAttribute(fkan_hmma, cudaFuncAttributeMaxDynamicSharedMemorySize, DYN_SMEM);
    fkan_hmma<<<dim3(SPLITK, 8, 2), 256, DYN_SMEM>>>(x, fc);
    fkan_reduce<<<512, 512>>>(bias, out);
}

// round 8
// speedup vs baseline: 3.3449x; 1.0528x over previous
#include <cuda_runtime.h>
#include <cstdint>
#include <math.h>

// NaiveFourierKANLayer via warp-level fp16 mma.sync, 2-term split:
//   y = sum_k Ah(k) * (Bh(k) + Bl(k)),  A = cos/sin generated fp16,
//   B = coeffs * 2048 split hi/lo fp16.
// R8: 512 threads / 16 warps (4 per SMSP) for latency hiding; warp tile 64x16.

#define NI 256
#define NG 300
#define NO 256
#define SPLITK 8
#define IPC (NI/SPLITK)      // 32 i per CTA
#define NGC 10               // 32-g chunks per i (chunk 9 zero-padded)

#define RSB 144              // smem row pitch bytes -> conflict-free ldmatrix
#define A_HI 0
#define B_HI 18432
#define B_LO 36864
#define STAGE_BYTES 55296
#define DYN_SMEM (2*STAGE_BYTES)   // 110592

#define BSCALE 2048.0f
#define FSCALE (1.0f/2048.0f)

__device__ float g_scratch[SPLITK * 1024 * 256];   // 8 MB split-K partials

// ---------------- helpers ----------------
__device__ __forceinline__ uint32_t smem_u32(const void* p) {
    uint32_t a;
    asm("{ .reg .u64 t; cvta.to.shared.u64 t, %1; cvt.u32.u64 %0, t; }" : "=r"(a) : "l"(p));
    return a;
}
// packf16(a,b): low f16 = a (even k), high f16 = b (odd k)
__device__ __forceinline__ uint32_t packf16(float a, float b) {
    uint32_t r;
    asm("cvt.rn.f16x2.f32 %0, %2, %1;" : "=r"(r) : "f"(a), "f"(b));
    return r;
}
__device__ __forceinline__ void unpackf16(uint32_t p, float& lo, float& hi) {
    asm("{ .reg .b16 l,h; mov.b32 {l,h}, %2; cvt.f32.f16 %0, l; cvt.f32.f16 %1, h; }"
        : "=f"(lo), "=f"(hi) : "r"(p));
}
__device__ __forceinline__ void rotstep(float& c, float& s, float cr, float sr) {
    float nc = fmaf(c, cr, -(s * sr));
    float ns = fmaf(s, cr, c * sr);
    c = nc; s = ns;
}

#define LDSM4(r0,r1,r2,r3,addr)                                                  \
    asm volatile("ldmatrix.sync.aligned.m8n8.x4.shared.b16 {%0,%1,%2,%3}, [%4];" \
        : "=r"(r0), "=r"(r1), "=r"(r2), "=r"(r3) : "r"(addr))

#define MMA(d,a,b0,b1)                                                        \
    asm volatile("mma.sync.aligned.m16n8k16.row.col.f32.f16.f16.f32 "         \
        "{%0,%1,%2,%3},{%4,%5,%6,%7},{%8,%9},{%0,%1,%2,%3};"                  \
        : "+f"((d)[0]), "+f"((d)[1]), "+f"((d)[2]), "+f"((d)[3])              \
        : "r"((a)[0]), "r"((a)[1]), "r"((a)[2]), "r"((a)[3]), "r"(b0), "r"(b1))

extern __shared__ char dsmem[];

__global__ void __launch_bounds__(512, 1)
fkan_hmma(const float* __restrict__ x, const float* __restrict__ fc)
{
    const int tid  = threadIdx.x;
    const int lane = tid & 31;
    const int w    = tid >> 5;            // 0..15
    const int ks = blockIdx.x;            // split-K slice (i block)
    const int m0 = blockIdx.y * 128;      // batch-row tile
    const int n0 = blockIdx.z * 128;      // output-col tile

    const uint32_t smb = smem_u32(dsmem);

    // ---- producer maps (512 threads) ----
    // A-gen: 128 rows x 2 g-halves x 2 sub-octets; 4 pairs (8 g) per thread
    const int rr = tid >> 2, q = (tid >> 1) & 1, sub = tid & 1;
    // B: 2 trig x 128 j x 2 16-g halves; 16 fp32 per thread
    const int bt = tid >> 8, bj = (tid >> 1) & 127, bhf = tid & 1;

    // ---- mma maps: 16 warps = 2(M) x 8(N); warp tile 64x16 ----
    const int wm = w & 1, wn = w >> 1;
    const uint32_t aoff = (uint32_t)(wm*64 + (lane & 7) + ((lane >> 3) & 1)*8) * RSB
                        + (uint32_t)(lane >> 4) * 16;
    const uint32_t boff = (uint32_t)(wn*16 + (lane & 7) + (lane >> 4)*8) * RSB
                        + (uint32_t)((lane >> 3) & 1) * 16;

    float acc[4][2][4];
    #pragma unroll
    for (int a = 0; a < 4; ++a)
        #pragma unroll
        for (int b = 0; b < 2; ++b)
            #pragma unroll
            for (int c = 0; c < 4; ++c) acc[a][b][c] = 0.f;

    const float* xcol  = x + (size_t)(m0 + rr) * NI + ks * IPC;
    const float* bbase = fc + ((size_t)(bt * NO + n0 + bj) * NI + ks * IPC) * NG
                       + bhf * 16;

    // B stage prefetch registers (16 fp32 per thread)
    float4 bf[4];
    #pragma unroll
    for (int q4 = 0; q4 < 4; ++q4) bf[q4] = *(const float4*)(bbase + q4 * 4);

    int it = 0;
    for (int ii = 0; ii < IPC; ++ii) {
        // rotation setup for this i
        const float t = xcol[ii];
        float s1, c1;
        sincosf(t, &s1, &c1);
        const float c2 = fmaf(c1, c1, -(s1*s1)), s2 = 2.f*c1*s1;
        const float c4 = fmaf(c2, c2, -(s2*s2)), s4 = 2.f*c2*s2;
        const float c8 = fmaf(c4, c4, -(s4*s4)), s8 = 2.f*c4*s4;
        const float c16 = fmaf(c8, c8, -(s8*s8)), s16 = 2.f*c8*s8;
        // state at angle (q*16 + sub*8 + 1)*t
        float cc = c1, ss = s1;
        if (sub) rotstep(cc, ss, c8, s8);
        if (q)   rotstep(cc, ss, c16, s16);

        for (int gc = 0; gc < NGC; ++gc, ++it) {
            char* sm = dsmem + (it & 1) * STAGE_BYTES;

            // ---- STS B (from prefetched regs, x2048, hi/lo) ----
            {
                const float* bv = (const float*)bf;
                #pragma unroll
                for (int pp = 0; pp < 8; ++pp) {
                    const float a = bv[2*pp] * BSCALE, b = bv[2*pp+1] * BSCALE;
                    const uint32_t hp = packf16(a, b);
                    float alo, bhi;
                    unpackf16(hp, alo, bhi);
                    const uint32_t lp = packf16(a - alo, b - bhi);
                    const uint32_t off = (uint32_t)bj * RSB
                                       + (uint32_t)(bt*32 + bhf*16 + 2*pp) * 2;
                    *(uint32_t*)(sm + B_HI + off) = hp;
                    *(uint32_t*)(sm + B_LO + off) = lp;
                }
            }
            // ---- generate + STS A: 4 adjacent pairs; cos k=gl, sin k=32+gl ----
            #pragma unroll
            for (int m = 0; m < 4; ++m) {
                const int gl = q*16 + sub*8 + 2*m;
                const int gg = gc*32 + gl;          // harmonic gg+1
                float ce = cc, se = ss;
                float co = fmaf(cc, c1, -(ss*s1));
                float so = fmaf(ss, c1,  cc*s1);
                if (gg     >= NG) { ce = 0.f; se = 0.f; }
                if (gg + 1 >= NG) { co = 0.f; so = 0.f; }
                const uint32_t offc = (uint32_t)rr * RSB + (uint32_t)gl * 2;
                *(uint32_t*)(sm + A_HI + offc)      = packf16(ce, co);
                *(uint32_t*)(sm + A_HI + offc + 64) = packf16(se, so);
                rotstep(cc, ss, c2, s2);            // +2t
            }
            // advance +24t (8 done of 32-g chunk stride)
            rotstep(cc, ss, c16, s16);
            rotstep(cc, ss, c8, s8);

            __syncthreads();

            // ---- prefetch next stage's B (hidden under HMMA) ----
            if (it + 1 < IPC * NGC) {
                const int nit = it + 1;
                const int nii = nit / NGC, ngc = nit % NGC;
                const float* p = bbase + (size_t)nii * NG + ngc * 32;
                #pragma unroll
                for (int q4 = 0; q4 < 4; ++q4) {
                    const int gg = ngc*32 + bhf*16 + q4*4;
                    bf[q4] = (gg + 3 < NG) ? *(const float4*)(p + q4*4)
                                           : make_float4(0.f, 0.f, 0.f, 0.f);
                }
            }

            // ---- consume: 4 K-steps x (4 mf x 2 nf) x 2 terms ----
            // gc==9: kk=1 (k12..31) and kk=3 (k44..63) are all-zero -> skip
            const uint32_t pA = smb + (uint32_t)(it & 1) * STAGE_BYTES + aoff;
            const uint32_t pB = smb + (uint32_t)(it & 1) * STAGE_BYTES + B_HI + boff;
            const int kkstep = (gc == 9) ? 2 : 1;
            #pragma unroll 4
            for (int kk = 0; kk < 4; kk += kkstep) {
                uint32_t bh4[4], bl4[4];
                LDSM4(bh4[0], bh4[1], bh4[2], bh4[3], pB + kk*32);
                LDSM4(bl4[0], bl4[1], bl4[2], bl4[3], pB + (B_LO - B_HI) + kk*32);
                uint32_t ah[4][4];
                #pragma unroll
                for (int mf = 0; mf < 4; ++mf)
                    LDSM4(ah[mf][0], ah[mf][1], ah[mf][2], ah[mf][3],
                          pA + mf*(16*RSB) + kk*32);
                #pragma unroll
                for (int mf = 0; mf < 4; ++mf) {
                    MMA(acc[mf][0], ah[mf], bh4[0], bh4[1]);   // Ah*Bhi nf0
                    MMA(acc[mf][1], ah[mf], bh4[2], bh4[3]);   // Ah*Bhi nf1
                }
                #pragma unroll
                for (int mf = 0; mf < 4; ++mf) {
                    MMA(acc[mf][0], ah[mf], bl4[0], bl4[1]);   // Ah*Blo nf0
                    MMA(acc[mf][1], ah[mf], bl4[2], bl4[3]);   // Ah*Blo nf1
                }
            }
        }
    }

    // ---- epilogue: accumulators (x2048) -> split-K scratch ----
    float* dst = g_scratch + ((size_t)ks << 18);
    #pragma unroll
    for (int mf = 0; mf < 4; ++mf) {
        const int r = m0 + wm*64 + mf*16 + (lane >> 2);
        #pragma unroll
        for (int nf = 0; nf < 2; ++nf) {
            const int c = n0 + wn*16 + nf*8 + (lane & 3)*2;
            float2 v0, v1;
            v0.x = acc[mf][nf][0] * FSCALE; v0.y = acc[mf][nf][1] * FSCALE;
            v1.x = acc[mf][nf][2] * FSCALE; v1.y = acc[mf][nf][3] * FSCALE;
            *(float2*)(dst + (size_t)r * NO + c)       = v0;
            *(float2*)(dst + (size_t)(r + 8) * NO + c) = v1;
        }
    }
}

__global__ void __launch_bounds__(512, 1)
fkan_reduce(const float* __restrict__ bias, float* __restrict__ out)
{
    const int idx = blockIdx.x * 512 + threadIdx.x;
    float a = bias[idx & 255];
    #pragma unroll
    for (int k = 0; k < SPLITK; ++k)
        a += g_scratch[((size_t)k << 18) + idx];
    out[idx] = a;
}

extern "C" void kernel_launch(void* const* d_in, const int* in_sizes, int n_in,
                              void* d_out, int out_size) {
    const float* x    = (const float*)d_in[0];
    const float* fc   = (const float*)d_in[1];
    const float* bias = (const float*)d_in[2];
    float* out        = (float*)d_out;

    cudaFuncSetAttribute(fkan_hmma, cudaFuncAttributeMaxDynamicSharedMemorySize, DYN_SMEM);
    fkan_hmma<<<dim3(SPLITK, 8, 2), 512, DYN_SMEM>>>(x, fc);
    fkan_reduce<<<512, 512>>>(bias, out);
}

// round 9
// speedup vs baseline: 3.8764x; 1.1589x over previous
#include <cuda_runtime.h>
#include <cstdint>
#include <math.h>

// NaiveFourierKANLayer via warp-level fp16 mma.sync, SINGLE term:
//   y = sum_k Ah(k) * Bh(k),  A = cos/sin generated fp16 (rotation recurrence),
//   B = coeffs * 2048 as single fp16 (scale keeps values in normal range).
// R9: halves MMA instruction count vs R8 (the binding resource: SIMT HMMA
// pipe floor ~512 MACs/cyc/SM measured across R4/R7/R8).

#define NI 256
#define NG 300
#define NO 256
#define SPLITK 8
#define IPC (NI/SPLITK)      // 32 i per CTA
#define NGC 10               // 32-g chunks per i (chunk 9 zero-padded)

#define RSB 144              // smem row pitch bytes -> conflict-free ldmatrix
#define A_HI 0
#define B_HI 18432
#define STAGE_BYTES 36864
#define DYN_SMEM (2*STAGE_BYTES)   // 73728

#define BSCALE 2048.0f
#define FSCALE (1.0f/2048.0f)

__device__ float g_scratch[SPLITK * 1024 * 256];   // 8 MB split-K partials

// ---------------- helpers ----------------
__device__ __forceinline__ uint32_t smem_u32(const void* p) {
    uint32_t a;
    asm("{ .reg .u64 t; cvta.to.shared.u64 t, %1; cvt.u32.u64 %0, t; }" : "=r"(a) : "l"(p));
    return a;
}
// packf16(a,b): low f16 = a (even k), high f16 = b (odd k)
__device__ __forceinline__ uint32_t packf16(float a, float b) {
    uint32_t r;
    asm("cvt.rn.f16x2.f32 %0, %2, %1;" : "=r"(r) : "f"(a), "f"(b));
    return r;
}
__device__ __forceinline__ void rotstep(float& c, float& s, float cr, float sr) {
    float nc = fmaf(c, cr, -(s * sr));
    float ns = fmaf(s, cr, c * sr);
    c = nc; s = ns;
}

#define LDSM4(r0,r1,r2,r3,addr)                                                  \
    asm volatile("ldmatrix.sync.aligned.m8n8.x4.shared.b16 {%0,%1,%2,%3}, [%4];" \
        : "=r"(r0), "=r"(r1), "=r"(r2), "=r"(r3) : "r"(addr))

#define MMA(d,a,b0,b1)                                                        \
    asm volatile("mma.sync.aligned.m16n8k16.row.col.f32.f16.f16.f32 "         \
        "{%0,%1,%2,%3},{%4,%5,%6,%7},{%8,%9},{%0,%1,%2,%3};"                  \
        : "+f"((d)[0]), "+f"((d)[1]), "+f"((d)[2]), "+f"((d)[3])              \
        : "r"((a)[0]), "r"((a)[1]), "r"((a)[2]), "r"((a)[3]), "r"(b0), "r"(b1))

extern __shared__ char dsmem[];

__global__ void __launch_bounds__(512, 1)
fkan_hmma(const float* __restrict__ x, const float* __restrict__ fc)
{
    const int tid  = threadIdx.x;
    const int lane = tid & 31;
    const int w    = tid >> 5;            // 0..15
    const int ks = blockIdx.x;            // split-K slice (i block)
    const int m0 = blockIdx.y * 128;      // batch-row tile
    const int n0 = blockIdx.z * 128;      // output-col tile

    const uint32_t smb = smem_u32(dsmem);

    // ---- producer maps (512 threads) ----
    // A-gen: 128 rows x 2 g-halves x 2 sub-octets; 4 pairs (8 g) per thread
    const int rr = tid >> 2, q = (tid >> 1) & 1, sub = tid & 1;
    // B: 2 trig x 128 j x 2 16-g halves; 16 fp32 per thread
    const int bt = tid >> 8, bj = (tid >> 1) & 127, bhf = tid & 1;

    // ---- mma maps: 16 warps = 2(M) x 8(N); warp tile 64x16 ----
    const int wm = w & 1, wn = w >> 1;
    const uint32_t aoff = (uint32_t)(wm*64 + (lane & 7) + ((lane >> 3) & 1)*8) * RSB
                        + (uint32_t)(lane >> 4) * 16;
    const uint32_t boff = (uint32_t)(wn*16 + (lane & 7) + (lane >> 4)*8) * RSB
                        + (uint32_t)((lane >> 3) & 1) * 16;

    float acc[4][2][4];
    #pragma unroll
    for (int a = 0; a < 4; ++a)
        #pragma unroll
        for (int b = 0; b < 2; ++b)
            #pragma unroll
            for (int c = 0; c < 4; ++c) acc[a][b][c] = 0.f;

    const float* xcol  = x + (size_t)(m0 + rr) * NI + ks * IPC;
    const float* bbase = fc + ((size_t)(bt * NO + n0 + bj) * NI + ks * IPC) * NG
                       + bhf * 16;

    // B stage prefetch registers (16 fp32 per thread)
    float4 bf[4];
    #pragma unroll
    for (int q4 = 0; q4 < 4; ++q4) bf[q4] = *(const float4*)(bbase + q4 * 4);

    int it = 0;
    for (int ii = 0; ii < IPC; ++ii) {
        // rotation setup for this i
        const float t = xcol[ii];
        float s1, c1;
        sincosf(t, &s1, &c1);
        const float c2 = fmaf(c1, c1, -(s1*s1)), s2 = 2.f*c1*s1;
        const float c4 = fmaf(c2, c2, -(s2*s2)), s4 = 2.f*c2*s2;
        const float c8 = fmaf(c4, c4, -(s4*s4)), s8 = 2.f*c4*s4;
        const float c16 = fmaf(c8, c8, -(s8*s8)), s16 = 2.f*c8*s8;
        // state at angle (q*16 + sub*8 + 1)*t
        float cc = c1, ss = s1;
        if (sub) rotstep(cc, ss, c8, s8);
        if (q)   rotstep(cc, ss, c16, s16);

        for (int gc = 0; gc < NGC; ++gc, ++it) {
            char* sm = dsmem + (it & 1) * STAGE_BYTES;

            // ---- STS B (from prefetched regs, x2048, single fp16) ----
            {
                const float* bv = (const float*)bf;
                #pragma unroll
                for (int pp = 0; pp < 8; ++pp) {
                    const uint32_t hp = packf16(bv[2*pp] * BSCALE, bv[2*pp+1] * BSCALE);
                    const uint32_t off = (uint32_t)bj * RSB
                                       + (uint32_t)(bt*32 + bhf*16 + 2*pp) * 2;
                    *(uint32_t*)(sm + B_HI + off) = hp;
                }
            }
            // ---- generate + STS A: 4 adjacent pairs; cos k=gl, sin k=32+gl ----
            #pragma unroll
            for (int m = 0; m < 4; ++m) {
                const int gl = q*16 + sub*8 + 2*m;
                const int gg = gc*32 + gl;          // harmonic gg+1
                float ce = cc, se = ss;
                float co = fmaf(cc, c1, -(ss*s1));
                float so = fmaf(ss, c1,  cc*s1);
                if (gg     >= NG) { ce = 0.f; se = 0.f; }
                if (gg + 1 >= NG) { co = 0.f; so = 0.f; }
                const uint32_t offc = (uint32_t)rr * RSB + (uint32_t)gl * 2;
                *(uint32_t*)(sm + A_HI + offc)      = packf16(ce, co);
                *(uint32_t*)(sm + A_HI + offc + 64) = packf16(se, so);
                rotstep(cc, ss, c2, s2);            // +2t
            }
            // advance +24t (8 done of 32-g chunk stride)
            rotstep(cc, ss, c16, s16);
            rotstep(cc, ss, c8, s8);

            __syncthreads();

            // ---- prefetch next stage's B (hidden under HMMA) ----
            if (it + 1 < IPC * NGC) {
                const int nit = it + 1;
                const int nii = nit / NGC, ngc = nit % NGC;
                const float* p = bbase + (size_t)nii * NG + ngc * 32;
                #pragma unroll
                for (int q4 = 0; q4 < 4; ++q4) {
                    const int gg = ngc*32 + bhf*16 + q4*4;
                    bf[q4] = (gg + 3 < NG) ? *(const float4*)(p + q4*4)
                                           : make_float4(0.f, 0.f, 0.f, 0.f);
                }
            }

            // ---- consume: 4 K-steps x (4 mf x 2 nf), single term ----
            // gc==9: kk=1 (k12..31) and kk=3 (k44..63) are all-zero -> skip
            const uint32_t pA = smb + (uint32_t)(it & 1) * STAGE_BYTES + aoff;
            const uint32_t pB = smb + (uint32_t)(it & 1) * STAGE_BYTES + B_HI + boff;
            const int kkstep = (gc == 9) ? 2 : 1;
            #pragma unroll 4
            for (int kk = 0; kk < 4; kk += kkstep) {
                uint32_t bh4[4];
                LDSM4(bh4[0], bh4[1], bh4[2], bh4[3], pB + kk*32);
                uint32_t ah[4][4];
                #pragma unroll
                for (int mf = 0; mf < 4; ++mf)
                    LDSM4(ah[mf][0], ah[mf][1], ah[mf][2], ah[mf][3],
                          pA + mf*(16*RSB) + kk*32);
                #pragma unroll
                for (int mf = 0; mf < 4; ++mf) {
                    MMA(acc[mf][0], ah[mf], bh4[0], bh4[1]);   // nf0
                    MMA(acc[mf][1], ah[mf], bh4[2], bh4[3]);   // nf1
                }
            }
        }
    }

    // ---- epilogue: accumulators (x2048) -> split-K scratch ----
    float* dst = g_scratch + ((size_t)ks << 18);
    #pragma unroll
    for (int mf = 0; mf < 4; ++mf) {
        const int r = m0 + wm*64 + mf*16 + (lane >> 2);
        #pragma unroll
        for (int nf = 0; nf < 2; ++nf) {
            const int c = n0 + wn*16 + nf*8 + (lane & 3)*2;
            float2 v0, v1;
            v0.x = acc[mf][nf][0] * FSCALE; v0.y = acc[mf][nf][1] * FSCALE;
            v1.x = acc[mf][nf][2] * FSCALE; v1.y = acc[mf][nf][3] * FSCALE;
            *(float2*)(dst + (size_t)r * NO + c)       = v0;
            *(float2*)(dst + (size_t)(r + 8) * NO + c) = v1;
        }
    }
}

__global__ void __launch_bounds__(512, 1)
fkan_reduce(const float* __restrict__ bias, float* __restrict__ out)
{
    const int idx = blockIdx.x * 512 + threadIdx.x;
    float a = bias[idx & 255];
    #pragma unroll
    for (int k = 0; k < SPLITK; ++k)
        a += g_scratch[((size_t)k << 18) + idx];
    out[idx] = a;
}

extern "C" void kernel_launch(void* const* d_in, const int* in_sizes, int n_in,
                              void* d_out, int out_size) {
    const float* x    = (const float*)d_in[0];
    const float* fc   = (const float*)d_in[1];
    const float* bias = (const float*)d_in[2];
    float* out        = (float*)d_out;

    cudaFuncSetAttribute(fkan_hmma, cudaFuncAttributeMaxDynamicSharedMemorySize, DYN_SMEM);
    fkan_hmma<<<dim3(SPLITK, 8, 2), 512, DYN_SMEM>>>(x, fc);
    fkan_reduce<<<512, 512>>>(bias, out);
}

// round 10
// speedup vs baseline: 4.5137x; 1.1644x over previous
#include <cuda_runtime.h>
#include <cstdint>
#include <math.h>

// NaiveFourierKANLayer via warp-level fp16 mma.sync, single term, WARP-SPECIALIZED:
//   warps 0-7  : producers (A = cos/sin rotation recurrence -> fp16 STS,
//                B = coeffs*2048 -> fp16 STS, B prefetch LDG)
//   warps 8-15 : consumers (ldmatrix + mma, 128x128 tile, warp tile 64x32)
// Double-buffered smem, one bar.sync per stage -> produce(s+1) overlaps consume(s).

#define NI 256
#define NG 300
#define NO 256
#define SPLITK 8
#define IPC (NI/SPLITK)      // 32 i per CTA
#define NGC 10               // 32-g chunks per i (chunk 9 zero-padded)
#define NSTAGE (IPC*NGC)     // 320

#define RSB 144              // smem row pitch bytes -> conflict-free ldmatrix
#define A_HI 0
#define B_HI 18432
#define STAGE_BYTES 36864
#define DYN_SMEM (2*STAGE_BYTES)   // 73728

#define BSCALE 2048.0f
#define FSCALE (1.0f/2048.0f)

__device__ float g_scratch[SPLITK * 1024 * 256];   // 8 MB split-K partials

// ---------------- helpers ----------------
__device__ __forceinline__ uint32_t smem_u32(const void* p) {
    uint32_t a;
    asm("{ .reg .u64 t; cvta.to.shared.u64 t, %1; cvt.u32.u64 %0, t; }" : "=r"(a) : "l"(p));
    return a;
}
// packf16(a,b): low f16 = a (even k), high f16 = b (odd k)
__device__ __forceinline__ uint32_t packf16(float a, float b) {
    uint32_t r;
    asm("cvt.rn.f16x2.f32 %0, %2, %1;" : "=r"(r) : "f"(a), "f"(b));
    return r;
}
__device__ __forceinline__ void rotstep(float& c, float& s, float cr, float sr) {
    float nc = fmaf(c, cr, -(s * sr));
    float ns = fmaf(s, cr, c * sr);
    c = nc; s = ns;
}

#define BARRIER() asm volatile("bar.sync 0;" ::: "memory")

#define LDSM4(r0,r1,r2,r3,addr)                                                  \
    asm volatile("ldmatrix.sync.aligned.m8n8.x4.shared.b16 {%0,%1,%2,%3}, [%4];" \
        : "=r"(r0), "=r"(r1), "=r"(r2), "=r"(r3) : "r"(addr))

#define MMA(d,a,b0,b1)                                                        \
    asm volatile("mma.sync.aligned.m16n8k16.row.col.f32.f16.f16.f32 "         \
        "{%0,%1,%2,%3},{%4,%5,%6,%7},{%8,%9},{%0,%1,%2,%3};"                  \
        : "+f"((d)[0]), "+f"((d)[1]), "+f"((d)[2]), "+f"((d)[3])              \
        : "r"((a)[0]), "r"((a)[1]), "r"((a)[2]), "r"((a)[3]), "r"(b0), "r"(b1))

extern __shared__ char dsmem[];

__global__ void __launch_bounds__(512, 1)
fkan_hmma(const float* __restrict__ x, const float* __restrict__ fc)
{
    const int tid  = threadIdx.x;
    const int lane = tid & 31;
    const int w    = tid >> 5;            // 0..15
    const int ks = blockIdx.x;            // split-K slice (i block)
    const int m0 = blockIdx.y * 128;      // batch-row tile
    const int n0 = blockIdx.z * 128;      // output-col tile

    const uint32_t smb = smem_u32(dsmem);

    if (w < 8) {
        // ================= PRODUCER (256 threads) =================
        // A-gen: 128 rows x 2 g-halves of 16; B: 2 trig x 128 j, 32 fp32 each
        const int rr = tid >> 1, q = tid & 1;
        const int bt = tid >> 7, bj = tid & 127;

        const float* xcol  = x + (size_t)(m0 + rr) * NI + ks * IPC;
        const float* bbase = fc + ((size_t)(bt * NO + n0 + bj) * NI + ks * IPC) * NG;

        float4 bf[8];
        #pragma unroll
        for (int q4 = 0; q4 < 8; ++q4) bf[q4] = *(const float4*)(bbase + q4 * 4);

        float c1 = 0.f, s1 = 0.f, c2 = 0.f, s2 = 0.f, c16 = 0.f, s16 = 0.f;
        float cc = 0.f, ss = 0.f;
        int pii = 0, pgc = 0;

        for (int ps = 0; ps < NSTAGE; ++ps) {
            if (pgc == 0) {
                const float t = xcol[pii];
                sincosf(t, &s1, &c1);
                c2 = fmaf(c1, c1, -(s1*s1)); s2 = 2.f*c1*s1;
                const float c4 = fmaf(c2, c2, -(s2*s2)), s4 = 2.f*c2*s2;
                const float c8 = fmaf(c4, c4, -(s4*s4)), s8 = 2.f*c4*s4;
                c16 = fmaf(c8, c8, -(s8*s8)); s16 = 2.f*c8*s8;
                cc = c1; ss = s1;                       // angle 1t
                if (q) rotstep(cc, ss, c16, s16);       // angle 17t
            }
            char* sm = dsmem + (ps & 1) * STAGE_BYTES;

            // ---- A: 8 adjacent-g pairs; cos at k=gl, sin at k=32+gl ----
            #pragma unroll
            for (int m = 0; m < 8; ++m) {
                const int gl = q*16 + 2*m;
                const int gg = pgc*32 + gl;             // harmonic gg+1
                float ce = cc, se = ss;
                float co = fmaf(cc, c1, -(ss*s1));
                float so = fmaf(ss, c1,  cc*s1);
                if (gg     >= NG) { ce = 0.f; se = 0.f; }
                if (gg + 1 >= NG) { co = 0.f; so = 0.f; }
                const uint32_t offc = (uint32_t)rr * RSB + (uint32_t)gl * 2;
                *(uint32_t*)(sm + A_HI + offc)      = packf16(ce, co);
                *(uint32_t*)(sm + A_HI + offc + 64) = packf16(se, so);
                rotstep(cc, ss, c2, s2);                // +2t
            }
            rotstep(cc, ss, c16, s16);                  // +16t -> next 32-g chunk

            // ---- B: STS 16 u32 from prefetched regs (x2048, single fp16) ----
            {
                const float* bv = (const float*)bf;
                #pragma unroll
                for (int pp = 0; pp < 16; ++pp) {
                    const uint32_t hp = packf16(bv[2*pp] * BSCALE, bv[2*pp+1] * BSCALE);
                    const uint32_t off = (uint32_t)bj * RSB + (uint32_t)(bt*32 + 2*pp) * 2;
                    *(uint32_t*)(sm + B_HI + off) = hp;
                }
            }

            // advance stage counters, then prefetch B for next stage
            if (++pgc == NGC) { pgc = 0; ++pii; }
            if (ps + 1 < NSTAGE) {
                const float* p = bbase + (size_t)pii * NG + pgc * 32;
                #pragma unroll
                for (int q4 = 0; q4 < 8; ++q4) {
                    const int gg = pgc*32 + q4*4;
                    bf[q4] = (gg + 3 < NG) ? *(const float4*)(p + q4*4)
                                           : make_float4(0.f, 0.f, 0.f, 0.f);
                }
            }
            BARRIER();
        }
    } else {
        // ================= CONSUMER (8 warps, 2M x 4N, warp tile 64x32) =================
        const int wc = w - 8;
        const int wm = wc & 1, wn = wc >> 1;
        const uint32_t aoff = (uint32_t)(wm*64 + (lane & 7) + ((lane >> 3) & 1)*8) * RSB
                            + (uint32_t)(lane >> 4) * 16;
        const uint32_t boff = (uint32_t)(wn*32 + (lane & 7) + (lane >> 4)*8) * RSB
                            + (uint32_t)((lane >> 3) & 1) * 16;

        float acc[4][4][4];
        #pragma unroll
        for (int a = 0; a < 4; ++a)
            #pragma unroll
            for (int b = 0; b < 4; ++b)
                #pragma unroll
                for (int c = 0; c < 4; ++c) acc[a][b][c] = 0.f;

        int cgc = 0;
        for (int it = 0; it < NSTAGE; ++it) {
            BARRIER();                               // stage it is full
            const uint32_t base = smb + (uint32_t)(it & 1) * STAGE_BYTES;
            const uint32_t pA = base + aoff;
            const uint32_t pB = base + B_HI + boff;
            const int kkstep = (cgc == 9) ? 2 : 1;   // zero-padded sub-steps skipped
            #pragma unroll 4
            for (int kk = 0; kk < 4; kk += kkstep) {
                uint32_t bh[8];
                LDSM4(bh[0], bh[1], bh[2], bh[3], pB + kk*32);
                LDSM4(bh[4], bh[5], bh[6], bh[7], pB + 16*RSB + kk*32);
                uint32_t ah[4][4];
                #pragma unroll
                for (int mf = 0; mf < 4; ++mf)
                    LDSM4(ah[mf][0], ah[mf][1], ah[mf][2], ah[mf][3],
                          pA + mf*(16*RSB) + kk*32);
                #pragma unroll
                for (int mf = 0; mf < 4; ++mf)
                    #pragma unroll
                    for (int f = 0; f < 4; ++f) {
                        const int bi = (f >> 1)*4 + (f & 1)*2;
                        MMA(acc[mf][f], ah[mf], bh[bi], bh[bi+1]);
                    }
            }
            if (++cgc == NGC) cgc = 0;
        }

        // ---- epilogue: accumulators (x2048) -> split-K scratch ----
        float* dst = g_scratch + ((size_t)ks << 18);
        #pragma unroll
        for (int mf = 0; mf < 4; ++mf) {
            const int r = m0 + wm*64 + mf*16 + (lane >> 2);
            #pragma unroll
            for (int f = 0; f < 4; ++f) {
                const int c = n0 + wn*32 + f*8 + (lane & 3)*2;
                float2 v0, v1;
                v0.x = acc[mf][f][0] * FSCALE; v0.y = acc[mf][f][1] * FSCALE;
                v1.x = acc[mf][f][2] * FSCALE; v1.y = acc[mf][f][3] * FSCALE;
                *(float2*)(dst + (size_t)r * NO + c)       = v0;
                *(float2*)(dst + (size_t)(r + 8) * NO + c) = v1;
            }
        }
    }
}

__global__ void __launch_bounds__(512, 1)
fkan_reduce(const float* __restrict__ bias, float* __restrict__ out)
{
    const int idx = blockIdx.x * 512 + threadIdx.x;
    float a = bias[idx & 255];
    #pragma unroll
    for (int k = 0; k < SPLITK; ++k)
        a += g_scratch[((size_t)k << 18) + idx];
    out[idx] = a;
}

extern "C" void kernel_launch(void* const* d_in, const int* in_sizes, int n_in,
                              void* d_out, int out_size) {
    const float* x    = (const float*)d_in[0];
    const float* fc   = (const float*)d_in[1];
    const float* bias = (const float*)d_in[2];
    float* out        = (float*)d_out;

    cudaFuncSetAttribute(fkan_hmma, cudaFuncAttributeMaxDynamicSharedMemorySize, DYN_SMEM);
    fkan_hmma<<<dim3(SPLITK, 8, 2), 512, DYN_SMEM>>>(x, fc);
    fkan_reduce<<<512, 512>>>(bias, out);
}